// round 16
// baseline (speedup 1.0000x reference)
#include <cuda_runtime.h>
#include <cuda_fp16.h>
#include <math.h>

#define NSIDE 512
#define NPIX  (512*512)
#define NF    257

typedef __half2 h2;

// ---- scratch ----
__device__ __align__(16) h2     g_tmp[NF * NPIX];   // row-pass out, [f][x][y], complex fp16
__device__ __align__(16) __half g_m[NF * NPIX];     // modulus*512, [f][x][y], fp16
__device__ float g_gram[32 * 16 * 24];
__device__ float g_a2;
__device__ uint2 g_twh[512];                        // fp16 twiddles {(c,c),(-s,s)}

__device__ __forceinline__ unsigned h2u(h2 a){ return *reinterpret_cast<unsigned*>(&a); }
__device__ __forceinline__ h2 u2h(unsigned a){ return *reinterpret_cast<h2*>(&a); }
__device__ __forceinline__ h2 hswap(h2 a){ return __lowhigh2highlow(a); }

#define DECL_H_CONSTS \
  const h2 PI2 = __floats2half2_rn(-1.f, 1.f); \
  const h2 MI2 = __floats2half2_rn(1.f, -1.f); \
  const h2 CCh = __floats2half2_rn(0.70710678118654752440f, 0.70710678118654752440f); \
  const h2 NCC = __floats2half2_rn(-0.70710678118654752440f, 0.70710678118654752440f);

// 8-pt DFT, +i sign, natural order, fp16 AoS complex (one h2 = one complex)
__device__ __forceinline__ void fft8h(h2 v[8], h2 PI2, h2 MI2, h2 CCh, h2 NCC) {
  h2 es0 = __hadd2(v[0], v[4]), ed0 = __hsub2(v[0], v[4]);
  h2 es1 = __hadd2(v[2], v[6]), ed1 = __hsub2(v[2], v[6]);
  h2 E0 = __hadd2(es0, es1), E2 = __hsub2(es0, es1);
  h2 sd1 = hswap(ed1);
  h2 E1 = __hfma2(sd1, PI2, ed0);
  h2 E3 = __hfma2(sd1, MI2, ed0);
  h2 os0 = __hadd2(v[1], v[5]), od0 = __hsub2(v[1], v[5]);
  h2 os1 = __hadd2(v[3], v[7]), od1 = __hsub2(v[3], v[7]);
  h2 O0 = __hadd2(os0, os1), O2 = __hsub2(os0, os1);
  h2 sod = hswap(od1);
  h2 O1 = __hfma2(sod, PI2, od0);
  h2 O3 = __hfma2(sod, MI2, od0);
  h2 t1 = __hfma2(hswap(O1), PI2, O1);
  h2 O1t = __hmul2(t1, CCh);
  h2 O2t = __hmul2(hswap(O2), PI2);
  h2 t2 = __hfma2(hswap(O3), PI2, O3);
  h2 O3t = __hmul2(hswap(t2), NCC);
  v[0] = __hadd2(E0, O0);  v[4] = __hsub2(E0, O0);
  v[1] = __hadd2(E1, O1t); v[5] = __hsub2(E1, O1t);
  v[2] = __hadd2(E2, O2t); v[6] = __hsub2(E2, O2t);
  v[3] = __hadd2(E3, O3t); v[7] = __hsub2(E3, O3t);
}

__device__ __forceinline__ h2 ctwh(h2 a, uint2 w) {   // a * (c + i s)
  return __hfma2(hswap(a), u2h(w.y), __hmul2(a, u2h(w.x)));
}

// 8x8 transpose among 8 lanes differing in low-3 lane bits (32-bit shuffles)
__device__ __forceinline__ void transpose8h(h2 v[8], int f3) {
#pragma unroll
  for (int mb = 0; mb < 3; mb++) {
    const int m = 1 << mb;
#pragma unroll
    for (int i = 0; i < 8; i++) {
      if ((i & m) == 0) {
        const int ip = i | m;
        const bool hi = (f3 & m) != 0;
        unsigned send = h2u(hi ? v[i] : v[ip]);
        unsigned got = __shfl_xor_sync(0xffffffffu, send, m);
        if (hi) v[i] = u2h(got); else v[ip] = u2h(got);
      }
    }
  }
}

__global__ void init_kernel() {
  int t = threadIdx.x;
  for (int m = t; m < 512; m += 256) {
    float s, c;
    sincospif((float)m * (1.0f / 256.0f), &s, &c);
    h2 wc = __floats2half2_rn(c, c), ws = __floats2half2_rn(-s, s);
    g_twh[m] = make_uint2(h2u(wc), h2u(ws));
  }
  for (int i = t; i < 32 * 384; i += 256) g_gram[i] = 0.f;
  if (t == 0) g_a2 = 0.f;
}

// ---- stage 1: product + 512-pt IFFT along x (fp16 AoS); transposed store [f][x][y] ----
// 16 rows per block (two 8-row FFT passes); store with 16-lane groups -> 64 B per line-touch.
__global__ void __launch_bounds__(512) rows_kernel(const float2* __restrict__ xh2,
                                                   const float* __restrict__ pre,
                                                   const float* __restrict__ pim) {
  __shared__ h2 S[4608];        // FFT exchange: 8 rows * 576  (18 KB)
  __shared__ h2 S2[512 * 18];   // transpose staging: [x][16 y + 2 pad]  (36 KB)
  DECL_H_CONSTS
  const int tid = threadIdx.x;
  const int row = tid >> 6, t = tid & 63;
  const int f = blockIdx.y;
  const int y0 = blockIdx.x << 4;   // 16 rows per block
  const size_t fb = (size_t)f * NPIX;

#pragma unroll 1
  for (int g = 0; g < 2; g++) {
    const size_t rowoff = (size_t)(y0 + g * 8 + row) * NSIDE;
    const size_t pb = fb + rowoff;
    h2 v[8];
#pragma unroll
    for (int q = 0; q < 8; q++) {
      int x = t + (q << 6);
      float2 xc = xh2[rowoff + x];
      float pr = __ldcs(pre + pb + x), pq = __ldcs(pim + pb + x);
      v[q] = __floats2half2_rn(xc.x * pr - xc.y * pq, xc.x * pq + xc.y * pr);
    }
    fft8h(v, PI2, MI2, CCh, NCC);
    h2* Sr = S + row * 576;
    Sr[t] = v[0];
#pragma unroll
    for (int r = 1; r < 8; r++)
      Sr[r * 72 + t] = ctwh(v[r], g_twh[t * r]);
    __syncthreads();

    const int r = t >> 3, T = t & 7;
#pragma unroll
    for (int q = 0; q < 8; q++)
      v[q] = Sr[r * 72 + T + (q << 3)];
    fft8h(v, PI2, MI2, CCh, NCC);
#pragma unroll
    for (int rp = 1; rp < 8; rp++)
      v[rp] = ctwh(v[rp], g_twh[8 * T * rp]);
    transpose8h(v, T);
    fft8h(v, PI2, MI2, CCh, NCC);

#pragma unroll
    for (int k3 = 0; k3 < 8; k3++) {
      int x = (k3 << 6) + t;
      S2[x * 18 + g * 8 + row] = v[k3];
    }
    __syncthreads();   // S2 writes done; S reusable for next g
  }

  // cooperative store: 16 lanes per x, 64 B per line-touch
  const int c = tid & 15, xi0 = tid >> 4;   // xi0: 0..31
#pragma unroll
  for (int k = 0; k < 16; k++) {
    int x = xi0 + (k << 5);
    ((unsigned*)(g_tmp + fb + (size_t)x * NSIDE + y0))[c] = h2u(S2[x * 18 + c]);
  }
}

// ---- stage 2: 512-pt IFFT along y (fp16 AoS, contiguous) + scaled modulus ----
__global__ void __launch_bounds__(256) cols_kernel() {
  __shared__ h2 S[4 * 576];
  __shared__ float red[8];
  DECL_H_CONSTS
  const int tid = threadIdx.x;
  const int cc = tid >> 6, t = tid & 63;
  const int f = NF - 1 - blockIdx.y;
  const int x = (blockIdx.x << 2) + cc;
  const size_t colbase = (size_t)f * NPIX + (size_t)x * NSIDE;

  h2 v[8];
#pragma unroll
  for (int q = 0; q < 8; q++)
    v[q] = g_tmp[colbase + t + (q << 6)];
  fft8h(v, PI2, MI2, CCh, NCC);
  h2* Sr = S + cc * 576;
  Sr[t] = v[0];
#pragma unroll
  for (int r = 1; r < 8; r++)
    Sr[r * 72 + t] = ctwh(v[r], g_twh[t * r]);
  __syncthreads();

  const int r = t >> 3, T = t & 7;
#pragma unroll
  for (int q = 0; q < 8; q++)
    v[q] = Sr[r * 72 + T + (q << 3)];
  fft8h(v, PI2, MI2, CCh, NCC);
#pragma unroll
  for (int rp = 1; rp < 8; rp++)
    v[rp] = ctwh(v[rp], g_twh[8 * T * rp]);
  transpose8h(v, T);
  fft8h(v, PI2, MI2, CCh, NCC);

  const float inv = 1.0f / (float)NPIX;
  float a2loc = 0.f;
#pragma unroll
  for (int k3 = 0; k3 < 8; k3++) {
    float2 a = __half22float2(v[k3]);
    float re = a.x * inv, im = a.y * inv;
    float h = sqrtf(re * re + im * im + 1e-8f) * 512.0f;
    if (f == 0) a2loc += h * h;
    g_m[colbase + (k3 << 6) + t] = __float2half_rn(h);
  }
  if (f == 0) {
    int lane = tid & 31, wp = tid >> 5;
    a2loc += __shfl_down_sync(0xffffffffu, a2loc, 16);
    a2loc += __shfl_down_sync(0xffffffffu, a2loc, 8);
    a2loc += __shfl_down_sync(0xffffffffu, a2loc, 4);
    a2loc += __shfl_down_sync(0xffffffffu, a2loc, 2);
    a2loc += __shfl_down_sync(0xffffffffu, a2loc, 1);
    if (lane == 0) red[wp] = a2loc;
    __syncthreads();
    if (tid == 0) {
      float s = 0.f;
#pragma unroll
      for (int w2 = 0; w2 < 8; w2++) s += red[w2];
      atomicAdd(&g_a2, s);
    }
  }
}

// ---- stage 3: all grams via HMMA, double-buffered pipeline ----
#define SB 1040

__device__ __forceinline__ void mma16816(float c[4], unsigned a0, unsigned a1, unsigned a2,
                                         unsigned a3, unsigned b0, unsigned b1) {
  asm volatile("mma.sync.aligned.m16n8k16.row.col.f32.f16.f16.f32 "
               "{%0,%1,%2,%3}, {%4,%5,%6,%7}, {%8,%9}, {%0,%1,%2,%3};"
               : "+f"(c[0]), "+f"(c[1]), "+f"(c[2]), "+f"(c[3])
               : "r"(a0), "r"(a1), "r"(a2), "r"(a3), "r"(b0), "r"(b1));
}

__global__ void __launch_bounds__(256) gram_kernel() {
  __shared__ __align__(16) unsigned char sm[2][24 * SB];
  const int g = blockIdx.x;
  const int tid = threadIdx.x;
  const int w = tid >> 5, lane = tid & 31;
  const bool jg = (g < 16);
  const size_t chunkbase = (size_t)blockIdx.y * 8192;

  for (int i = tid; i < 7 * 65; i += 256) {
    ((uint4*)(sm[0] + 17 * SB))[i] = make_uint4(0, 0, 0, 0);
    ((uint4*)(sm[1] + 17 * SB))[i] = make_uint4(0, 0, 0, 0);
  }

  const int ccc = tid & 63, rbase = tid >> 6;
  const uint4* src[5];
#pragma unroll
  for (int p = 0; p < 4; p++) {
    int rr = rbase + 4 * p;
    int fidx = jg ? (1 + rr * 16 + g) : (1 + (g - 16) * 16 + rr);
    src[p] = (const uint4*)(g_m + (size_t)fidx * NPIX) + ccc;
  }
  src[4] = (const uint4*)g_m + tid;
  const bool do_lp = jg && (tid < 64);

  float c0[4] = {0,0,0,0}, c1[4] = {0,0,0,0}, c2[4] = {0,0,0,0};

  unsigned smb[2] = { (unsigned)__cvta_generic_to_shared(sm[0]),
                      (unsigned)__cvta_generic_to_shared(sm[1]) };
  const unsigned arel = ((lane & 7) + ((lane >> 3) & 1) * 8) * SB + (lane >> 4) * 16;
  const unsigned lrel = (16 + (lane & 7)) * SB + ((lane >> 3) & 1) * 16;
  const unsigned pwarp = w * 128;
  const unsigned dst0 = rbase * SB + ccc * 16;

  uint4 rg[5];
  {
    const size_t P4 = chunkbase >> 3;
#pragma unroll
    for (int p = 0; p < 4; p++) rg[p] = src[p][P4];
    if (do_lp) rg[4] = src[4][P4];
#pragma unroll
    for (int p = 0; p < 4; p++)
      *(uint4*)(sm[0] + dst0 + p * 4 * SB) = rg[p];
    if (do_lp) *(uint4*)(sm[0] + 16 * SB + tid * 16) = rg[4];
  }
  __syncthreads();

  for (int it = 0; it < 16; it++) {
    const int b = it & 1;
    if (it < 15) {
      const size_t P4 = (chunkbase + (it + 1) * 512) >> 3;
#pragma unroll
      for (int p = 0; p < 4; p++) rg[p] = src[p][P4];
      if (do_lp) rg[4] = src[4][P4];
    }

#pragma unroll
    for (int ks = 0; ks < 4; ks++) {
      unsigned pb = pwarp + ks * 32;
      unsigned a0, a1, a2, a3;
      asm volatile("ldmatrix.sync.aligned.m8n8.x4.shared.b16 {%0,%1,%2,%3}, [%4];"
                   : "=r"(a0), "=r"(a1), "=r"(a2), "=r"(a3) : "r"(smb[b] + arel + pb));
      mma16816(c0, a0, a1, a2, a3, a0, a2);
      mma16816(c1, a0, a1, a2, a3, a1, a3);
      if (jg) {
        unsigned l0, l1;
        asm volatile("ldmatrix.sync.aligned.m8n8.x2.shared.b16 {%0,%1}, [%2];"
                     : "=r"(l0), "=r"(l1) : "r"(smb[b] + lrel + pb));
        mma16816(c2, a0, a1, a2, a3, l0, l1);
      }
    }

    if (it < 15) {
      unsigned char* dbuf = sm[1 - b];
#pragma unroll
      for (int p = 0; p < 4; p++)
        *(uint4*)(dbuf + dst0 + p * 4 * SB) = rg[p];
      if (do_lp) *(uint4*)(dbuf + 16 * SB + tid * 16) = rg[4];
    }
    __syncthreads();
  }

  float* Gs = (float*)sm;
  const int row0 = lane >> 2, colb = 2 * (lane & 3);
  float* W = Gs + w * 384;
  W[row0 * 24 + colb]            = c0[0];
  W[row0 * 24 + colb + 1]        = c0[1];
  W[(row0 + 8) * 24 + colb]      = c0[2];
  W[(row0 + 8) * 24 + colb + 1]  = c0[3];
  W[row0 * 24 + 8 + colb]        = c1[0];
  W[row0 * 24 + 8 + colb + 1]    = c1[1];
  W[(row0 + 8) * 24 + 8 + colb]     = c1[2];
  W[(row0 + 8) * 24 + 8 + colb + 1] = c1[3];
  W[row0 * 24 + 16 + colb]       = c2[0];
  W[row0 * 24 + 16 + colb + 1]   = c2[1];
  W[(row0 + 8) * 24 + 16 + colb]     = c2[2];
  W[(row0 + 8) * 24 + 16 + colb + 1] = c2[3];
  __syncthreads();
  for (int e = tid; e < 384; e += 256) {
    float s = 0.f;
#pragma unroll
    for (int w2 = 0; w2 < 8; w2++) s += Gs[w2 * 384 + e];
    atomicAdd(&g_gram[g * 384 + e], s);
  }
}

// ---- stage 4: assemble (reference ordering); scale 1/(NPIX*512^2) ----
__global__ void assemble_kernel(float* __restrict__ out) {
  const int t = threadIdx.x;
  const float inv = 1.0f / ((float)NPIX * 262144.0f);
  if (t == 0) out[0] = g_a2 * inv;
  if (t >= 256) return;
  int i = t >> 4, j = t & 15;
  int rowsum = 152 * i + 16 * (15 * i - (i * (i - 1)) / 2);
  int segsum = 2 * j + ((i < 15) ? (15 - i) * j : 0) + 15 * j - (j * (j - 1)) / 2;
  int pos = 1 + rowsum + segsum;
  const float* GA = g_gram + (j * 16 + i) * 24;
  out[pos++] = GA[i] * inv;
  out[pos++] = GA[16] * inv;
  if (i < 15)
    for (int l = i + 1; l < 16; l++)
      out[pos++] = g_gram[(j * 16 + i) * 24 + l] * inv;
  if (j < 15)
    for (int l = j + 1; l < 16; l++)
      out[pos++] = g_gram[((16 + i) * 16 + j) * 24 + l] * inv;
}

extern "C" void kernel_launch(void* const* d_in, const int* in_sizes, int n_in,
                              void* d_out, int out_size) {
  const float2* xh2 = (const float2*)d_in[0];
  const float* pre  = (const float*)d_in[1];
  const float* pim  = (const float*)d_in[2];
  float* out = (float*)d_out;

  init_kernel<<<1, 256>>>();
  rows_kernel<<<dim3(NSIDE / 16, NF), 512>>>(xh2, pre, pim);
  cols_kernel<<<dim3(NSIDE / 4, NF), 256>>>();
  gram_kernel<<<dim3(32, 32), 256>>>();
  assemble_kernel<<<1, 256>>>(out);
}

// round 17
// speedup vs baseline: 1.1816x; 1.1816x over previous
#include <cuda_runtime.h>
#include <cuda_fp16.h>
#include <math.h>

#define NSIDE 512
#define NPIX  (512*512)
#define NF    257

typedef __half2 h2;

// ---- scratch ----
__device__ __align__(16) h2     g_tmp[NF * NPIX];   // row-pass out, [f][x][y], complex fp16
__device__ __align__(16) __half g_m[NF * NPIX];     // modulus*512, [f][x][y], fp16
__device__ float g_gram[32 * 16 * 24];
__device__ float g_a2;
__device__ uint2 g_twh[512];                        // fp16 twiddles {(c,c),(-s,s)}

__device__ __forceinline__ unsigned h2u(h2 a){ return *reinterpret_cast<unsigned*>(&a); }
__device__ __forceinline__ h2 u2h(unsigned a){ return *reinterpret_cast<h2*>(&a); }
__device__ __forceinline__ h2 hswap(h2 a){ return __lowhigh2highlow(a); }

#define DECL_H_CONSTS \
  const h2 PI2 = __floats2half2_rn(-1.f, 1.f); \
  const h2 MI2 = __floats2half2_rn(1.f, -1.f); \
  const h2 CCh = __floats2half2_rn(0.70710678118654752440f, 0.70710678118654752440f); \
  const h2 NCC = __floats2half2_rn(-0.70710678118654752440f, 0.70710678118654752440f);

// 8-pt DFT, +i sign, natural order, fp16 AoS complex (one h2 = one complex)
__device__ __forceinline__ void fft8h(h2 v[8], h2 PI2, h2 MI2, h2 CCh, h2 NCC) {
  h2 es0 = __hadd2(v[0], v[4]), ed0 = __hsub2(v[0], v[4]);
  h2 es1 = __hadd2(v[2], v[6]), ed1 = __hsub2(v[2], v[6]);
  h2 E0 = __hadd2(es0, es1), E2 = __hsub2(es0, es1);
  h2 sd1 = hswap(ed1);
  h2 E1 = __hfma2(sd1, PI2, ed0);
  h2 E3 = __hfma2(sd1, MI2, ed0);
  h2 os0 = __hadd2(v[1], v[5]), od0 = __hsub2(v[1], v[5]);
  h2 os1 = __hadd2(v[3], v[7]), od1 = __hsub2(v[3], v[7]);
  h2 O0 = __hadd2(os0, os1), O2 = __hsub2(os0, os1);
  h2 sod = hswap(od1);
  h2 O1 = __hfma2(sod, PI2, od0);
  h2 O3 = __hfma2(sod, MI2, od0);
  h2 t1 = __hfma2(hswap(O1), PI2, O1);
  h2 O1t = __hmul2(t1, CCh);
  h2 O2t = __hmul2(hswap(O2), PI2);
  h2 t2 = __hfma2(hswap(O3), PI2, O3);
  h2 O3t = __hmul2(hswap(t2), NCC);
  v[0] = __hadd2(E0, O0);  v[4] = __hsub2(E0, O0);
  v[1] = __hadd2(E1, O1t); v[5] = __hsub2(E1, O1t);
  v[2] = __hadd2(E2, O2t); v[6] = __hsub2(E2, O2t);
  v[3] = __hadd2(E3, O3t); v[7] = __hsub2(E3, O3t);
}

__device__ __forceinline__ h2 ctwh(h2 a, uint2 w) {   // a * (c + i s)
  return __hfma2(hswap(a), u2h(w.y), __hmul2(a, u2h(w.x)));
}

// 8x8 transpose among 8 lanes differing in low-3 lane bits (32-bit shuffles)
__device__ __forceinline__ void transpose8h(h2 v[8], int f3) {
#pragma unroll
  for (int mb = 0; mb < 3; mb++) {
    const int m = 1 << mb;
#pragma unroll
    for (int i = 0; i < 8; i++) {
      if ((i & m) == 0) {
        const int ip = i | m;
        const bool hi = (f3 & m) != 0;
        unsigned send = h2u(hi ? v[i] : v[ip]);
        unsigned got = __shfl_xor_sync(0xffffffffu, send, m);
        if (hi) v[i] = u2h(got); else v[ip] = u2h(got);
      }
    }
  }
}

__global__ void init_kernel() {
  int t = threadIdx.x;
  for (int m = t; m < 512; m += 256) {
    float s, c;
    sincospif((float)m * (1.0f / 256.0f), &s, &c);
    h2 wc = __floats2half2_rn(c, c), ws = __floats2half2_rn(-s, s);
    g_twh[m] = make_uint2(h2u(wc), h2u(ws));
  }
  for (int i = t; i < 32 * 384; i += 256) g_gram[i] = 0.f;
  if (t == 0) g_a2 = 0.f;
}

// ---- stage 1: product + 512-pt IFFT along x (fp16 AoS); transposed store [f][x][y] ----
// Store stage: 8 lanes cooperate per x -> 4 lines per STG.32 (R15 WIN config).
__global__ void __launch_bounds__(512) rows_kernel(const float2* __restrict__ xh2,
                                                   const float* __restrict__ pre,
                                                   const float* __restrict__ pim) {
  __shared__ h2 S[5120];   // 20 KB: FFT stage 8*576; transpose stage stride 9
  DECL_H_CONSTS
  const int tid = threadIdx.x;
  const int row = tid >> 6, t = tid & 63;
  const int f = blockIdx.y;
  const int y0 = blockIdx.x << 3;
  const size_t rowoff = (size_t)(y0 + row) * NSIDE;
  const size_t fb = (size_t)f * NPIX + rowoff;

  h2 v[8];
#pragma unroll
  for (int q = 0; q < 8; q++) {
    int x = t + (q << 6);
    float2 xc = xh2[rowoff + x];
    float pr = __ldcs(pre + fb + x), pq = __ldcs(pim + fb + x);
    v[q] = __floats2half2_rn(xc.x * pr - xc.y * pq, xc.x * pq + xc.y * pr);
  }
  fft8h(v, PI2, MI2, CCh, NCC);
  h2* Sr = S + row * 576;
  Sr[t] = v[0];
#pragma unroll
  for (int r = 1; r < 8; r++)
    Sr[r * 72 + t] = ctwh(v[r], g_twh[t * r]);
  __syncthreads();

  const int r = t >> 3, T = t & 7;
#pragma unroll
  for (int q = 0; q < 8; q++)
    v[q] = Sr[r * 72 + T + (q << 3)];
  fft8h(v, PI2, MI2, CCh, NCC);
#pragma unroll
  for (int rp = 1; rp < 8; rp++)
    v[rp] = ctwh(v[rp], g_twh[8 * T * rp]);
  transpose8h(v, T);
  fft8h(v, PI2, MI2, CCh, NCC);
  __syncthreads();

#pragma unroll
  for (int k3 = 0; k3 < 8; k3++)
    S[((k3 << 6) + t) * 9 + row] = v[k3];
  __syncthreads();

  // cooperative store: lane group of 8 per x, 4 lines per STG.32
  const size_t fxb = (size_t)f * NPIX;
  const int xi = tid >> 3, c = tid & 7;
#pragma unroll
  for (int k = 0; k < 8; k++) {
    int x = xi + (k << 6);
    ((unsigned*)(g_tmp + fxb + (size_t)x * NSIDE + y0))[c] = h2u(S[x * 9 + c]);
  }
}

// ---- stage 2: 512-pt IFFT along y (fp16 AoS, contiguous) + scaled modulus ----
__global__ void __launch_bounds__(256) cols_kernel() {
  __shared__ h2 S[4 * 576];
  __shared__ float red[8];
  DECL_H_CONSTS
  const int tid = threadIdx.x;
  const int cc = tid >> 6, t = tid & 63;
  const int f = NF - 1 - blockIdx.y;
  const int x = (blockIdx.x << 2) + cc;
  const size_t colbase = (size_t)f * NPIX + (size_t)x * NSIDE;

  h2 v[8];
#pragma unroll
  for (int q = 0; q < 8; q++)
    v[q] = g_tmp[colbase + t + (q << 6)];
  fft8h(v, PI2, MI2, CCh, NCC);
  h2* Sr = S + cc * 576;
  Sr[t] = v[0];
#pragma unroll
  for (int r = 1; r < 8; r++)
    Sr[r * 72 + t] = ctwh(v[r], g_twh[t * r]);
  __syncthreads();

  const int r = t >> 3, T = t & 7;
#pragma unroll
  for (int q = 0; q < 8; q++)
    v[q] = Sr[r * 72 + T + (q << 3)];
  fft8h(v, PI2, MI2, CCh, NCC);
#pragma unroll
  for (int rp = 1; rp < 8; rp++)
    v[rp] = ctwh(v[rp], g_twh[8 * T * rp]);
  transpose8h(v, T);
  fft8h(v, PI2, MI2, CCh, NCC);

  const float inv = 1.0f / (float)NPIX;
  float a2loc = 0.f;
#pragma unroll
  for (int k3 = 0; k3 < 8; k3++) {
    float2 a = __half22float2(v[k3]);
    float re = a.x * inv, im = a.y * inv;
    float h = sqrtf(re * re + im * im + 1e-8f) * 512.0f;
    if (f == 0) a2loc += h * h;
    g_m[colbase + (k3 << 6) + t] = __float2half_rn(h);
  }
  if (f == 0) {
    int lane = tid & 31, wp = tid >> 5;
    a2loc += __shfl_down_sync(0xffffffffu, a2loc, 16);
    a2loc += __shfl_down_sync(0xffffffffu, a2loc, 8);
    a2loc += __shfl_down_sync(0xffffffffu, a2loc, 4);
    a2loc += __shfl_down_sync(0xffffffffu, a2loc, 2);
    a2loc += __shfl_down_sync(0xffffffffu, a2loc, 1);
    if (lane == 0) red[wp] = a2loc;
    __syncthreads();
    if (tid == 0) {
      float s = 0.f;
#pragma unroll
      for (int w2 = 0; w2 < 8; w2++) s += red[w2];
      atomicAdd(&g_a2, s);
    }
  }
}

// ---- stage 3: all grams via HMMA; cp.async double-buffered pipeline ----
#define SB 1040

__device__ __forceinline__ void mma16816(float c[4], unsigned a0, unsigned a1, unsigned a2,
                                         unsigned a3, unsigned b0, unsigned b1) {
  asm volatile("mma.sync.aligned.m16n8k16.row.col.f32.f16.f16.f32 "
               "{%0,%1,%2,%3}, {%4,%5,%6,%7}, {%8,%9}, {%0,%1,%2,%3};"
               : "+f"(c[0]), "+f"(c[1]), "+f"(c[2]), "+f"(c[3])
               : "r"(a0), "r"(a1), "r"(a2), "r"(a3), "r"(b0), "r"(b1));
}

__device__ __forceinline__ void cp16(unsigned dst, const void* src) {
  asm volatile("cp.async.cg.shared.global [%0], [%1], 16;" :: "r"(dst), "l"(src) : "memory");
}

__global__ void __launch_bounds__(256) gram_kernel() {
  __shared__ __align__(16) unsigned char sm[2][24 * SB];
  const int g = blockIdx.x;
  const int tid = threadIdx.x;
  const int w = tid >> 5, lane = tid & 31;
  const bool jg = (g < 16);
  const size_t chunkbase = (size_t)blockIdx.y * 8192;

  for (int i = tid; i < 7 * 65; i += 256) {
    ((uint4*)(sm[0] + 17 * SB))[i] = make_uint4(0, 0, 0, 0);
    ((uint4*)(sm[1] + 17 * SB))[i] = make_uint4(0, 0, 0, 0);
  }

  const int ccc = tid & 63, rbase = tid >> 6;
  const uint4* src[5];
#pragma unroll
  for (int p = 0; p < 4; p++) {
    int rr = rbase + 4 * p;
    int fidx = jg ? (1 + rr * 16 + g) : (1 + (g - 16) * 16 + rr);
    src[p] = (const uint4*)(g_m + (size_t)fidx * NPIX) + ccc;
  }
  src[4] = (const uint4*)g_m + tid;
  const bool do_lp = jg && (tid < 64);

  float c0[4] = {0,0,0,0}, c1[4] = {0,0,0,0}, c2[4] = {0,0,0,0};

  unsigned smb[2] = { (unsigned)__cvta_generic_to_shared(sm[0]),
                      (unsigned)__cvta_generic_to_shared(sm[1]) };
  const unsigned arel = ((lane & 7) + ((lane >> 3) & 1) * 8) * SB + (lane >> 4) * 16;
  const unsigned lrel = (16 + (lane & 7)) * SB + ((lane >> 3) & 1) * 16;
  const unsigned pwarp = w * 128;
  const unsigned dst0 = rbase * SB + ccc * 16;

  // prologue: async-load chunk 0 into buffer 0
  {
    const size_t P4 = chunkbase >> 3;
#pragma unroll
    for (int p = 0; p < 4; p++)
      cp16(smb[0] + dst0 + p * 4 * SB, src[p] + P4);
    if (do_lp) cp16(smb[0] + 16 * SB + tid * 16, src[4] + P4);
    asm volatile("cp.async.commit_group;" ::: "memory");
    asm volatile("cp.async.wait_group 0;" ::: "memory");
  }
  __syncthreads();

  for (int it = 0; it < 16; it++) {
    const int b = it & 1;
    if (it < 15) {
      const size_t P4 = (chunkbase + (it + 1) * 512) >> 3;
      const unsigned db = smb[1 - b];
#pragma unroll
      for (int p = 0; p < 4; p++)
        cp16(db + dst0 + p * 4 * SB, src[p] + P4);
      if (do_lp) cp16(db + 16 * SB + tid * 16, src[4] + P4);
      asm volatile("cp.async.commit_group;" ::: "memory");
    }

#pragma unroll
    for (int ks = 0; ks < 4; ks++) {
      unsigned pb = pwarp + ks * 32;
      unsigned a0, a1, a2, a3;
      asm volatile("ldmatrix.sync.aligned.m8n8.x4.shared.b16 {%0,%1,%2,%3}, [%4];"
                   : "=r"(a0), "=r"(a1), "=r"(a2), "=r"(a3) : "r"(smb[b] + arel + pb));
      mma16816(c0, a0, a1, a2, a3, a0, a2);
      mma16816(c1, a0, a1, a2, a3, a1, a3);
      if (jg) {
        unsigned l0, l1;
        asm volatile("ldmatrix.sync.aligned.m8n8.x2.shared.b16 {%0,%1}, [%2];"
                     : "=r"(l0), "=r"(l1) : "r"(smb[b] + lrel + pb));
        mma16816(c2, a0, a1, a2, a3, l0, l1);
      }
    }

    if (it < 15)
      asm volatile("cp.async.wait_group 0;" ::: "memory");
    __syncthreads();
  }

  float* Gs = (float*)sm;
  const int row0 = lane >> 2, colb = 2 * (lane & 3);
  float* W = Gs + w * 384;
  W[row0 * 24 + colb]            = c0[0];
  W[row0 * 24 + colb + 1]        = c0[1];
  W[(row0 + 8) * 24 + colb]      = c0[2];
  W[(row0 + 8) * 24 + colb + 1]  = c0[3];
  W[row0 * 24 + 8 + colb]        = c1[0];
  W[row0 * 24 + 8 + colb + 1]    = c1[1];
  W[(row0 + 8) * 24 + 8 + colb]     = c1[2];
  W[(row0 + 8) * 24 + 8 + colb + 1] = c1[3];
  W[row0 * 24 + 16 + colb]       = c2[0];
  W[row0 * 24 + 16 + colb + 1]   = c2[1];
  W[(row0 + 8) * 24 + 16 + colb]     = c2[2];
  W[(row0 + 8) * 24 + 16 + colb + 1] = c2[3];
  __syncthreads();
  for (int e = tid; e < 384; e += 256) {
    float s = 0.f;
#pragma unroll
    for (int w2 = 0; w2 < 8; w2++) s += Gs[w2 * 384 + e];
    atomicAdd(&g_gram[g * 384 + e], s);
  }
}

// ---- stage 4: assemble (reference ordering); scale 1/(NPIX*512^2) ----
__global__ void assemble_kernel(float* __restrict__ out) {
  const int t = threadIdx.x;
  const float inv = 1.0f / ((float)NPIX * 262144.0f);
  if (t == 0) out[0] = g_a2 * inv;
  if (t >= 256) return;
  int i = t >> 4, j = t & 15;
  int rowsum = 152 * i + 16 * (15 * i - (i * (i - 1)) / 2);
  int segsum = 2 * j + ((i < 15) ? (15 - i) * j : 0) + 15 * j - (j * (j - 1)) / 2;
  int pos = 1 + rowsum + segsum;
  const float* GA = g_gram + (j * 16 + i) * 24;
  out[pos++] = GA[i] * inv;
  out[pos++] = GA[16] * inv;
  if (i < 15)
    for (int l = i + 1; l < 16; l++)
      out[pos++] = g_gram[(j * 16 + i) * 24 + l] * inv;
  if (j < 15)
    for (int l = j + 1; l < 16; l++)
      out[pos++] = g_gram[((16 + i) * 16 + j) * 24 + l] * inv;
}

extern "C" void kernel_launch(void* const* d_in, const int* in_sizes, int n_in,
                              void* d_out, int out_size) {
  const float2* xh2 = (const float2*)d_in[0];
  const float* pre  = (const float*)d_in[1];
  const float* pim  = (const float*)d_in[2];
  float* out = (float*)d_out;

  init_kernel<<<1, 256>>>();
  rows_kernel<<<dim3(NSIDE / 8, NF), 512>>>(xh2, pre, pim);
  cols_kernel<<<dim3(NSIDE / 4, NF), 256>>>();
  gram_kernel<<<dim3(32, 32), 256>>>();
  assemble_kernel<<<1, 256>>>(out);
}